// round 7
// baseline (speedup 1.0000x reference)
#include <cuda_runtime.h>
#include <math.h>

#define N_IMG 32
#define ROWS_PER_IMG 262144              // 128*128*64 / 4 float4-rows per image
#define SLICES 32                        // CTAs per image
#define GCTAS 256                        // SLICES * IMGS_PER_ROUND
#define GTHREADS 512
#define IMGS_PER_ROUND 8
#define ROUNDS 4
#define ROWS_PER_CTA_F (ROWS_PER_IMG / SLICES)     // 8192
#define RPT (ROWS_PER_CTA_F / GTHREADS)            // 16 rows per thread

// Deterministic scratch (no device allocation allowed).
__device__ float    g_part[N_IMG][SLICES][14];
__device__ float    g_coef[N_IMG][8];
__device__ unsigned g_count[N_IMG];
__device__ unsigned g_flag[N_IMG];

// ---------------------------------------------------------------------------
// Reset barrier state each launch (graph replays reuse the globals).
// ---------------------------------------------------------------------------
__global__ void reset_kernel() {
    if (threadIdx.x < N_IMG) {
        g_count[threadIdx.x] = 0u;
        g_flag[threadIdx.x]  = 0u;
    }
}

// ---------------------------------------------------------------------------
// Single-thread solve: fp64 stats from shared moments, shifted gram
// E = Gram - N*I in fp64 (cancellation-safe), Jacobi in fp32 on E.
// Writes g_coef[img], then release-flags g_flag[img].
// ---------------------------------------------------------------------------
__device__ void solve_one(const double* red, int img) {
    const double N = (double)ROWS_PER_IMG;
    double S[4] = {red[0], red[1], red[2], red[3]};
    double Q[4][4];
    Q[0][0] = red[4];  Q[0][1] = red[5];  Q[0][2] = red[6];  Q[0][3] = red[7];
    Q[1][1] = red[8];  Q[1][2] = red[9];  Q[1][3] = red[10];
    Q[2][2] = red[11]; Q[2][3] = red[12]; Q[3][3] = red[13];
    Q[1][0] = Q[0][1]; Q[2][0] = Q[0][2]; Q[3][0] = Q[0][3];
    Q[2][1] = Q[1][2]; Q[3][1] = Q[1][3]; Q[3][2] = Q[2][3];

    double mu[4], inv[4];
    bool zerov[4];
#pragma unroll
    for (int i = 0; i < 4; i++) {
        mu[i] = S[i] / N;
        double var = Q[i][i] / N - mu[i] * mu[i];
        if (var < 0.0) var = 0.0;
        double sd = sqrt(var);
        zerov[i] = (sd == 0.0);
        inv[i] = zerov[i] ? 0.0 : 1.0 / sd;
    }

    float A[4][4];
    for (int i = 0; i < 4; i++)
        for (int j = 0; j < 4; j++) {
            double g = (Q[i][j] - N * mu[i] * mu[j]) * inv[i] * inv[j];
            if (i == j) g = zerov[i] ? -N : 0.0;
            A[i][j] = (float)g;
        }

    float V[4][4] = {{1,0,0,0},{0,1,0,0},{0,0,1,0},{0,0,0,1}};
    for (int sweep = 0; sweep < 8; sweep++) {
        float off = fabsf(A[0][1]) + fabsf(A[0][2]) + fabsf(A[0][3])
                  + fabsf(A[1][2]) + fabsf(A[1][3]) + fabsf(A[2][3]);
        if (off < 1e-3f) break;   // entries O(500); fp32 noise floor
        for (int p = 0; p < 3; p++) {
            for (int q = p + 1; q < 4; q++) {
                float apq = A[p][q];
                if (fabsf(apq) == 0.0f) continue;
                float theta = (A[q][q] - A[p][p]) / (2.0f * apq);
                float tt = ((theta >= 0.0f) ? 1.0f : -1.0f)
                         / (fabsf(theta) + sqrtf(theta * theta + 1.0f));
                float c = rsqrtf(tt * tt + 1.0f);
                float s = tt * c;
                for (int k = 0; k < 4; k++) {
                    float akp = A[k][p], akq = A[k][q];
                    A[k][p] = c * akp - s * akq;
                    A[k][q] = s * akp + c * akq;
                }
                for (int k = 0; k < 4; k++) {
                    float apk = A[p][k], aqk = A[q][k];
                    A[p][k] = c * apk - s * aqk;
                    A[q][k] = s * apk + c * aqk;
                }
                for (int k = 0; k < 4; k++) {
                    float vkp = V[k][p], vkq = V[k][q];
                    V[k][p] = c * vkp - s * vkq;
                    V[k][q] = s * vkp + c * vkq;
                }
            }
        }
    }

    int best = 0;
    for (int i = 1; i < 4; i++)
        if (A[i][i] > A[best][best]) best = i;

    float v[4]; float sum = 0.0f;
#pragma unroll
    for (int i = 0; i < 4; i++) { v[i] = V[i][best]; sum += v[i]; }
    double sgn = (sum < 0.0f) ? -1.0 : 1.0;

    double b = 0.0;
#pragma unroll
    for (int i = 0; i < 4; i++) {
        double wi = sgn * (double)v[i] * inv[i];
        g_coef[img][i] = (float)wi;
        b -= wi * mu[i];
    }
    g_coef[img][4] = (float)b;
    __threadfence();
    atomicExch(&g_flag[img], 1u);   // release
}

// ---------------------------------------------------------------------------
// Projection of one image-slice. Reads are L2 hits (data streamed <=2 rounds
// ago, ~<=70 MiB of intervening traffic vs 126 MB L2). Coefs fetched by t0
// after acquire-spin, broadcast via smem.
// ---------------------------------------------------------------------------
__device__ __forceinline__ void project_image(int img, int slice, int t,
                                              const float4* __restrict__ in,
                                              float* __restrict__ out,
                                              float* s_coef) {
    if (t == 0) {
        while (atomicAdd(&g_flag[img], 0u) == 0u) { __nanosleep(64); }
        __threadfence();   // acquire
#pragma unroll
        for (int i = 0; i < 5; i++) s_coef[i] = __ldcg(&g_coef[img][i]);
    }
    __syncthreads();
    const float w0 = s_coef[0], w1 = s_coef[1], w2c = s_coef[2],
                w3 = s_coef[3], bb = s_coef[4];
    const size_t ibase = (size_t)img * ROWS_PER_IMG;
    const int obase = slice * ROWS_PER_CTA_F;
#pragma unroll
    for (int k = 0; k < RPT; k++) {
        int lo = obase + k * GTHREADS + t;
        int S = lo >> 6, c_out = lo & 63;
        int h2 = S >> 6, w2i = S & 63;
        int pp = c_out >> 4, cg = c_out & 15;
        int ph = pp >> 1, pw = pp & 1;
        int m = (((h2 << 1) + ph) * 128 + ((w2i << 1) + pw)) * 16 + cg;
        float4 x = __ldg(in + ibase + m);
        __stcs(out + ibase + lo,
               fmaf(w0, x.x, fmaf(w1, x.y, fmaf(w2c, x.z, fmaf(w3, x.w, bb)))));
    }
}

// ---------------------------------------------------------------------------
// Fused persistent kernel. 256 CTAs x 512 threads, occ 2 => all resident
// (296 slots), software barriers are safe. 4 rounds of 8 images:
//   phase A: reduce this round's image slice, last CTA per image solves;
//   phase B: project the PREVIOUS round's image (coefs ready, data L2-hot).
// ---------------------------------------------------------------------------
__global__ void __launch_bounds__(GTHREADS, 2)
fused_kernel(const float4* __restrict__ in, float* __restrict__ out) {
    const int cta = blockIdx.x;
    const int t = threadIdx.x;
    const int lane = t & 31, warp = t >> 5;
    const int img_ir = cta >> 5;           // image within round
    const int slice  = cta & 31;

    __shared__ float    s_red[16][14];
    __shared__ double   s_m[14];
    __shared__ float    s_coef[5];
    __shared__ unsigned s_ticket;

    for (int r = 0; r < ROUNDS; r++) {
        const int img = (r << 3) + img_ir;

        // ---------------- phase A: reduce slice of img ----------------
        {
            const float4* p = in + (size_t)img * ROWS_PER_IMG
                                 + slice * ROWS_PER_CTA_F + t;
            float s0 = 0.f, s1 = 0.f, s2 = 0.f, s3 = 0.f;
            float q00 = 0.f, q01 = 0.f, q02 = 0.f, q03 = 0.f;
            float q11 = 0.f, q12 = 0.f, q13 = 0.f;
            float q22 = 0.f, q23 = 0.f, q33 = 0.f;

#pragma unroll
            for (int g = 0; g < RPT / 8; g++) {
                float4 buf[8];
#pragma unroll
                for (int j = 0; j < 8; j++)
                    buf[j] = __ldg(p + (g * 8 + j) * GTHREADS);
#pragma unroll
                for (int j = 0; j < 8; j++) {
                    float4 v = buf[j];
                    s0 += v.x; s1 += v.y; s2 += v.z; s3 += v.w;
                    q00 = fmaf(v.x, v.x, q00); q01 = fmaf(v.x, v.y, q01);
                    q02 = fmaf(v.x, v.z, q02); q03 = fmaf(v.x, v.w, q03);
                    q11 = fmaf(v.y, v.y, q11); q12 = fmaf(v.y, v.z, q12);
                    q13 = fmaf(v.y, v.w, q13);
                    q22 = fmaf(v.z, v.z, q22); q23 = fmaf(v.z, v.w, q23);
                    q33 = fmaf(v.w, v.w, q33);
                }
            }

            float vals[14] = {s0, s1, s2, s3, q00, q01, q02, q03,
                              q11, q12, q13, q22, q23, q33};
#pragma unroll
            for (int i = 0; i < 14; i++) {
                float v = vals[i];
#pragma unroll
                for (int off = 16; off; off >>= 1)
                    v += __shfl_down_sync(0xffffffffu, v, off);
                if (lane == 0) s_red[warp][i] = v;
            }
            __syncthreads();
            if (warp == 0 && lane < 14) {
                float v = 0.f;
#pragma unroll
                for (int w = 0; w < 16; w++) v += s_red[w][lane];
                g_part[img][slice][lane] = v;
            }
            __syncthreads();
            if (t == 0) {
                __threadfence();                      // publish partials
                s_ticket = atomicAdd(&g_count[img], 1u);
            }
            __syncthreads();
            if (s_ticket == SLICES - 1) {             // last CTA -> solver
                __threadfence();                      // acquire partials
                if (t < 14) {
                    double a = 0.0;
#pragma unroll 4
                    for (int s = 0; s < SLICES; s++)
                        a += (double)__ldcg(&g_part[img][s][t]);
                    s_m[t] = a;
                }
                __syncthreads();
                if (t == 0) solve_one(s_m, img);
            }
        }

        // ---------------- phase B: project previous round ----------------
        if (r > 0)
            project_image(((r - 1) << 3) + img_ir, slice, t, in, out, s_coef);
    }
    // tail: project the last round (solves just issued; brief spin at most)
    project_image(((ROUNDS - 1) << 3) + img_ir, slice, t, in, out, s_coef);
}

extern "C" void kernel_launch(void* const* d_in, const int* in_sizes, int n_in,
                              void* d_out, int out_size) {
    const float4* in = (const float4*)d_in[0];
    float* out = (float*)d_out;
    reset_kernel<<<1, 32>>>();
    fused_kernel<<<GCTAS, GTHREADS>>>(in, out);
}

// round 8
// speedup vs baseline: 2.3549x; 2.3549x over previous
#include <cuda_runtime.h>
#include <math.h>

#define N_IMG 32
#define ROWS_PER_IMG 262144              // 128*128*64 / 4 float4-rows per image
#define K1_CTAS_PER_IMG 64
#define K1_THREADS 256
#define ROWS_PER_CTA (ROWS_PER_IMG / K1_CTAS_PER_IMG)   // 4096
#define ROWS_PER_THREAD (ROWS_PER_CTA / K1_THREADS)     // 16
#define K1_BATCH 8

// Deterministic scratch (no device allocation allowed).
__device__ float g_part[N_IMG][K1_CTAS_PER_IMG][14];
__device__ float g_coef[N_IMG][8];   // w0..w3, b, pad

// ---------------------------------------------------------------------------
// K1: per-image raw moments. Every float4 of the image is one patches row.
// (Unchanged from the 66us round: 25.7us, 68% DRAM, 87% occ.)
// ---------------------------------------------------------------------------
__global__ void __launch_bounds__(K1_THREADS) k1_reduce(const float4* __restrict__ in) {
    const int img = blockIdx.x >> 6;
    const int cta = blockIdx.x & 63;
    const float4* p = in + (size_t)img * ROWS_PER_IMG + cta * ROWS_PER_CTA + threadIdx.x;

    float s0 = 0.f, s1 = 0.f, s2 = 0.f, s3 = 0.f;
    float q00 = 0.f, q01 = 0.f, q02 = 0.f, q03 = 0.f;
    float q11 = 0.f, q12 = 0.f, q13 = 0.f;
    float q22 = 0.f, q23 = 0.f, q33 = 0.f;

#pragma unroll
    for (int g = 0; g < ROWS_PER_THREAD / K1_BATCH; g++) {
        float4 buf[K1_BATCH];
#pragma unroll
        for (int j = 0; j < K1_BATCH; j++)
            buf[j] = __ldg(p + (g * K1_BATCH + j) * K1_THREADS);
#pragma unroll
        for (int j = 0; j < K1_BATCH; j++) {
            float4 v = buf[j];
            s0 += v.x; s1 += v.y; s2 += v.z; s3 += v.w;
            q00 = fmaf(v.x, v.x, q00); q01 = fmaf(v.x, v.y, q01);
            q02 = fmaf(v.x, v.z, q02); q03 = fmaf(v.x, v.w, q03);
            q11 = fmaf(v.y, v.y, q11); q12 = fmaf(v.y, v.z, q12);
            q13 = fmaf(v.y, v.w, q13);
            q22 = fmaf(v.z, v.z, q22); q23 = fmaf(v.z, v.w, q23);
            q33 = fmaf(v.w, v.w, q33);
        }
    }

    float vals[14] = {s0, s1, s2, s3, q00, q01, q02, q03, q11, q12, q13, q22, q23, q33};

    __shared__ float sm[8][14];
    const int lane = threadIdx.x & 31;
    const int warp = threadIdx.x >> 5;

#pragma unroll
    for (int i = 0; i < 14; i++) {
        float v = vals[i];
#pragma unroll
        for (int off = 16; off; off >>= 1)
            v += __shfl_down_sync(0xffffffffu, v, off);
        if (lane == 0) sm[warp][i] = v;
    }
    __syncthreads();
    if (warp == 0 && lane < 14) {
        float v = 0.f;
#pragma unroll
        for (int w = 0; w < 8; w++) v += sm[w][lane];
        g_part[img][cta][lane] = v;
    }
}

// ---------------------------------------------------------------------------
// K2: per-image final reduction (fp64, non-iterative), stats, then SHIFTED
// gram E = Gram - N*I in fp64 (cancellation-safe) and Jacobi in fp32 on E
// with a real convergence break. (Unchanged.)
// ---------------------------------------------------------------------------
__global__ void k2_solve() {
    const int img = blockIdx.x;
    const int t = threadIdx.x;
    __shared__ double red[14];

    if (t < 14) {
        double acc = 0.0;
#pragma unroll 4
        for (int c = 0; c < K1_CTAS_PER_IMG; c++)
            acc += (double)g_part[img][c][t];
        red[t] = acc;
    }
    __syncthreads();

    if (t == 0) {
        const double N = (double)ROWS_PER_IMG;
        double S[4] = {red[0], red[1], red[2], red[3]};
        double Q[4][4];
        Q[0][0] = red[4];  Q[0][1] = red[5];  Q[0][2] = red[6];  Q[0][3] = red[7];
        Q[1][1] = red[8];  Q[1][2] = red[9];  Q[1][3] = red[10];
        Q[2][2] = red[11]; Q[2][3] = red[12]; Q[3][3] = red[13];
        Q[1][0] = Q[0][1]; Q[2][0] = Q[0][2]; Q[3][0] = Q[0][3];
        Q[2][1] = Q[1][2]; Q[3][1] = Q[1][3]; Q[3][2] = Q[2][3];

        double mu[4], inv[4];
        bool zerov[4];
#pragma unroll
        for (int i = 0; i < 4; i++) {
            mu[i] = S[i] / N;
            double var = Q[i][i] / N - mu[i] * mu[i];
            if (var < 0.0) var = 0.0;
            double sd = sqrt(var);
            zerov[i] = (sd == 0.0);
            inv[i] = zerov[i] ? 0.0 : 1.0 / sd;
        }

        float A[4][4];
        for (int i = 0; i < 4; i++)
            for (int j = 0; j < 4; j++) {
                double g = (Q[i][j] - N * mu[i] * mu[j]) * inv[i] * inv[j];
                if (i == j) g = zerov[i] ? -N : 0.0;
                A[i][j] = (float)g;
            }

        float V[4][4] = {{1,0,0,0},{0,1,0,0},{0,0,1,0},{0,0,0,1}};
        for (int sweep = 0; sweep < 8; sweep++) {
            float off = fabsf(A[0][1]) + fabsf(A[0][2]) + fabsf(A[0][3])
                      + fabsf(A[1][2]) + fabsf(A[1][3]) + fabsf(A[2][3]);
            if (off < 1e-3f) break;   // entries O(500); fp32 noise floor
            for (int p = 0; p < 3; p++) {
                for (int q = p + 1; q < 4; q++) {
                    float apq = A[p][q];
                    if (fabsf(apq) == 0.0f) continue;
                    float theta = (A[q][q] - A[p][p]) / (2.0f * apq);
                    float tt = ((theta >= 0.0f) ? 1.0f : -1.0f)
                             / (fabsf(theta) + sqrtf(theta * theta + 1.0f));
                    float c = rsqrtf(tt * tt + 1.0f);
                    float s = tt * c;
                    for (int k = 0; k < 4; k++) {
                        float akp = A[k][p], akq = A[k][q];
                        A[k][p] = c * akp - s * akq;
                        A[k][q] = s * akp + c * akq;
                    }
                    for (int k = 0; k < 4; k++) {
                        float apk = A[p][k], aqk = A[q][k];
                        A[p][k] = c * apk - s * aqk;
                        A[q][k] = s * apk + c * aqk;
                    }
                    for (int k = 0; k < 4; k++) {
                        float vkp = V[k][p], vkq = V[k][q];
                        V[k][p] = c * vkp - s * vkq;
                        V[k][q] = s * vkp + c * vkq;
                    }
                }
            }
        }

        int best = 0;
        for (int i = 1; i < 4; i++)
            if (A[i][i] > A[best][best]) best = i;

        float v[4]; float sum = 0.0f;
#pragma unroll
        for (int i = 0; i < 4; i++) { v[i] = V[i][best]; sum += v[i]; }
        double sgn = (sum < 0.0f) ? -1.0 : 1.0;

        double b = 0.0;
#pragma unroll
        for (int i = 0; i < 4; i++) {
            double wi = sgn * (double)v[i] * inv[i];
            g_coef[img][i] = (float)wi;
            b -= wi * mu[i];
        }
        g_coef[img][4] = (float)b;
    }
}

// ---------------------------------------------------------------------------
// K3: projection, VECTORIZED 4 outputs/thread. Four consecutive c_out share
// (h2,w2,ph,pw) and map to 4 CONSECUTIVE input float4s: 4 independent
// LDG.128 in flight (MLP=4), one STG.128, index math amortized 4x.
// Reverse block order (MRU-first after K1's stream) + streaming stores kept.
// ---------------------------------------------------------------------------
__global__ void __launch_bounds__(256) k3_project(const float4* __restrict__ in,
                                                  float4* __restrict__ out) {
    const int blk = gridDim.x - 1 - blockIdx.x;          // reverse traversal
    const int o4 = blk * 256 + threadIdx.x;              // float4 output index
    const int img = o4 >> 16;          // 65536 float4-outputs per image
    const int lo4 = o4 & 65535;
    const int S  = lo4 >> 4;           // 16 float4 per (h2,w2) block
    const int c4 = lo4 & 15;           // which float4 within the 64 channels
    const int h2 = S >> 6, w2i = S & 63;
    const int pp = c4 >> 2;            // ph*2 + pw (4 c_out share one patch pos)
    const int cgb = (c4 & 3) << 2;     // base channel-group 0,4,8,12
    const int ph = pp >> 1, pw = pp & 1;
    const int m = (((h2 << 1) + ph) * 128 + ((w2i << 1) + pw)) * 16 + cgb;

    const float4* src = in + (size_t)img * ROWS_PER_IMG + m;
    float4 x0 = __ldg(src + 0);
    float4 x1 = __ldg(src + 1);
    float4 x2 = __ldg(src + 2);
    float4 x3 = __ldg(src + 3);

    const float* cf = g_coef[img];
    const float w0 = cf[0], w1 = cf[1], w2c = cf[2], w3 = cf[3], b = cf[4];

    float4 r;
    r.x = fmaf(w0, x0.x, fmaf(w1, x0.y, fmaf(w2c, x0.z, fmaf(w3, x0.w, b))));
    r.y = fmaf(w0, x1.x, fmaf(w1, x1.y, fmaf(w2c, x1.z, fmaf(w3, x1.w, b))));
    r.z = fmaf(w0, x2.x, fmaf(w1, x2.y, fmaf(w2c, x2.z, fmaf(w3, x2.w, b))));
    r.w = fmaf(w0, x3.x, fmaf(w1, x3.y, fmaf(w2c, x3.z, fmaf(w3, x3.w, b))));
    __stcs(out + o4, r);
}

extern "C" void kernel_launch(void* const* d_in, const int* in_sizes, int n_in,
                              void* d_out, int out_size) {
    const float4* in = (const float4*)d_in[0];
    float4* out = (float4*)d_out;
    k1_reduce<<<N_IMG * K1_CTAS_PER_IMG, K1_THREADS>>>(in);
    k2_solve<<<N_IMG, 64>>>();
    // 32*262144 float outputs / 4 per thread / 256 per block = 8192 blocks
    k3_project<<<(N_IMG * ROWS_PER_IMG) / 4 / 256, 256>>>(in, out);
}